// round 5
// baseline (speedup 1.0000x reference)
#include <cuda_runtime.h>

// Problem constants (fixed by the dataset)
#define NN   65536   // nodes
#define KCH  8       // children per node
#define HH   128     // hidden size
#define TT   4       // node types

// Scratch (allocation-free rule: __device__ globals)
__device__ float g_hsum[NN * HH];     // 32 MB: per-node child-sum of h
__device__ int   g_perm[TT * NN];     // per-type node index segments (capacity NN each)
__device__ int   g_cnt[TT];           // per-type counts

typedef unsigned long long ull;

// ---- packed f32x2 helpers (FFMA2: 2 MACs/instr on the fma pipe) ----
__device__ __forceinline__ void ffma2(ull& d, ull a, ull b) {
    asm("fma.rn.f32x2 %0, %1, %2, %0;" : "+l"(d) : "l"(a), "l"(b));
}
__device__ __forceinline__ ull bcast2(float x) {
    ull r; asm("mov.b64 %0, {%1, %1};" : "=l"(r) : "f"(x)); return r;
}
__device__ __forceinline__ float2 unpack2(ull v) {
    float2 f; asm("mov.b64 {%0, %1}, %2;" : "=f"(f.x), "=f"(f.y) : "l"(v)); return f;
}

// ---------------------------------------------------------------------------
// Kernel 1: zero per-type counters (graph-replay safe: re-zeroed every launch)
// ---------------------------------------------------------------------------
__global__ void k_zero() {
    if (threadIdx.x < TT) g_cnt[threadIdx.x] = 0;
}

// ---------------------------------------------------------------------------
// Kernel 2: bucket nodes by type. Block-aggregated atomics: 4 global atomics
// per 256-node block instead of 65536 global atomics.
// ---------------------------------------------------------------------------
__global__ void k_scatter(const int* __restrict__ type_id) {
    __shared__ int s_cnt[TT], s_base[TT], s_cur[TT];
    int tid = threadIdx.x;
    int n = blockIdx.x * 256 + tid;
    if (tid < TT) s_cnt[tid] = 0;
    __syncthreads();
    int t = type_id[n];
    atomicAdd(&s_cnt[t], 1);
    __syncthreads();
    if (tid < TT) {
        s_base[tid] = atomicAdd(&g_cnt[tid], s_cnt[tid]);
        s_cur[tid] = 0;
    }
    __syncthreads();
    int pos = atomicAdd(&s_cur[t], 1);
    g_perm[t * NN + s_base[t] + pos] = n;
}

// ---------------------------------------------------------------------------
// Kernel 3: h_sum[n, :] = sum_k h[n, k, :]   (vectorized float4, coalesced)
// ---------------------------------------------------------------------------
__global__ void k_hsum(const float* __restrict__ h) {
    int g = blockIdx.x * 256 + threadIdx.x;     // float4 index, total N*H/4 = 2M
    int n = g >> 5;                              // 32 float4 per node
    int i = g & 31;
    const float4* h4 = (const float4*)h;
    float4 s = h4[(size_t)n * 256 + i];
#pragma unroll
    for (int k = 1; k < KCH; ++k) {
        float4 v = h4[(size_t)n * 256 + k * 32 + i];
        s.x += v.x; s.y += v.y; s.z += v.z; s.w += v.w;
    }
    ((float4*)g_hsum)[g] = s;
}

// ---------------------------------------------------------------------------
// Kernel 4: grouped GEMM for iou = h_sum @ U_iou[t] + b_iou[t]
// Block tile: 128 nodes x 128 cols (3 col-chunks cover 384), K tiled by 32.
// Warp owns 16 rows; A reads are warp-broadcast LDS (conflict-free), B reads
// are contiguous 16B LDS; accumulation via FFMA2.
// ---------------------------------------------------------------------------
__global__ __launch_bounds__(256, 2)
void k_iou(const float* __restrict__ U_iou, const float* __restrict__ b_iou,
           float* __restrict__ out) {
    int t = blockIdx.z;
    int cnt = g_cnt[t];
    int m0 = blockIdx.x * 128;
    if (m0 >= cnt) return;
    int chunk = blockIdx.y;                 // 0..2 -> output cols chunk*128
    __shared__ float As[128 * 32];          // [row][k]   16 KB
    __shared__ float Bs[32 * 128];          // [k][col]   16 KB
    int tid = threadIdx.x;
    int w = tid >> 5, lane = tid & 31;
    const int* perm = g_perm + t * NN + m0;

    ull acc[16][2];
#pragma unroll
    for (int r = 0; r < 16; ++r) { acc[r][0] = 0ull; acc[r][1] = 0ull; }

    for (int kc = 0; kc < 4; ++kc) {
        __syncthreads();
        // --- load A tile: each warp loads its own 16 rows (32 floats each) ---
        {
            int i4 = lane & 7;      // float4 column within the 32-float row
            int rs = lane >> 3;     // 0..3
#pragma unroll
            for (int rr = 0; rr < 4; ++rr) {
                int row = w * 16 + rr * 4 + rs;
                float4 v = make_float4(0.f, 0.f, 0.f, 0.f);
                if (m0 + row < cnt) {
                    int n = perm[row];
                    v = *(const float4*)(g_hsum + (size_t)n * HH + kc * 32 + i4 * 4);
                }
                *(float4*)(As + row * 32 + i4 * 4) = v;
            }
        }
        // --- load B tile: U_iou[t][kc*32 + i][chunk*128 + j] ---
#pragma unroll
        for (int l = 0; l < 4; ++l) {
            int idx = l * 256 + tid;
            int i = idx >> 5, j4 = idx & 31;
            float4 v = *(const float4*)(U_iou + (size_t)t * HH * 384 +
                                        (size_t)(kc * 32 + i) * 384 + chunk * 128 + j4 * 4);
            *(float4*)(Bs + i * 128 + j4 * 4) = v;
        }
        __syncthreads();
        // --- compute ---
#pragma unroll
        for (int i4 = 0; i4 < 8; ++i4) {
            ulonglong2 b0 = *(const ulonglong2*)(Bs + (i4 * 4 + 0) * 128 + lane * 4);
            ulonglong2 b1 = *(const ulonglong2*)(Bs + (i4 * 4 + 1) * 128 + lane * 4);
            ulonglong2 b2 = *(const ulonglong2*)(Bs + (i4 * 4 + 2) * 128 + lane * 4);
            ulonglong2 b3 = *(const ulonglong2*)(Bs + (i4 * 4 + 3) * 128 + lane * 4);
#pragma unroll
            for (int r = 0; r < 16; ++r) {
                float4 a = *(const float4*)(As + (w * 16 + r) * 32 + i4 * 4);
                ull ax = bcast2(a.x), ay = bcast2(a.y), az = bcast2(a.z), aw = bcast2(a.w);
                ffma2(acc[r][0], ax, b0.x); ffma2(acc[r][1], ax, b0.y);
                ffma2(acc[r][0], ay, b1.x); ffma2(acc[r][1], ay, b1.y);
                ffma2(acc[r][0], az, b2.x); ffma2(acc[r][1], az, b2.y);
                ffma2(acc[r][0], aw, b3.x); ffma2(acc[r][1], aw, b3.y);
            }
        }
    }
    // --- epilogue: + b_iou, scatter to out[n, chunk*128 + j] ---
    float4 bi = *(const float4*)(b_iou + t * 384 + chunk * 128 + lane * 4);
#pragma unroll
    for (int r = 0; r < 16; ++r) {
        int mi = m0 + w * 16 + r;
        if (mi >= cnt) continue;
        int n = perm[w * 16 + r];
        float2 p0 = unpack2(acc[r][0]), p1 = unpack2(acc[r][1]);
        float4 o = make_float4(p0.x + bi.x, p0.y + bi.y, p1.x + bi.z, p1.y + bi.w);
        *(float4*)(out + (size_t)n * 512 + chunk * 128 + lane * 4) = o;
    }
}

// ---------------------------------------------------------------------------
// Kernel 5: grouped GEMM for forget-gate logits (rows = node*8 + child), fused
// sigmoid + f*c child-reduction epilogue.
// Block tile: 16 nodes (128 GEMM rows) x 128 cols, K tiled by 32.
// Warp owns rows w*16..w*16+15 = nodes {2w, 2w+1} (8 child-rows each), so the
// k-reduction stays entirely in the thread's own accumulators.
// ---------------------------------------------------------------------------
__global__ __launch_bounds__(256, 2)
void k_fgate(const float* __restrict__ h, const float* __restrict__ c,
             const float* __restrict__ f_input, const float* __restrict__ U_f,
             const float* __restrict__ b_f, float* __restrict__ out) {
    int t = blockIdx.z;
    int cnt = g_cnt[t];
    int m0 = blockIdx.x * 16;               // first node of this tile
    if (m0 >= cnt) return;
    __shared__ float As[128 * 32];
    __shared__ float Bs[32 * 128];
    int tid = threadIdx.x;
    int w = tid >> 5, lane = tid & 31;
    const int* perm = g_perm + t * NN + m0;

    ull acc[16][2];
#pragma unroll
    for (int r = 0; r < 16; ++r) { acc[r][0] = 0ull; acc[r][1] = 0ull; }

    for (int kc = 0; kc < 4; ++kc) {
        __syncthreads();
        // --- A tile: row = ln*8 + k ->  h[n_ln, k, kc*32 + i] ---
        {
            int i4 = lane & 7;
            int rs = lane >> 3;
#pragma unroll
            for (int rr = 0; rr < 4; ++rr) {
                int row = w * 16 + rr * 4 + rs;
                int ln = row >> 3, k = row & 7;
                float4 v = make_float4(0.f, 0.f, 0.f, 0.f);
                if (m0 + ln < cnt) {
                    int n = perm[ln];
                    v = *(const float4*)(h + (size_t)n * 1024 + k * 128 + kc * 32 + i4 * 4);
                }
                *(float4*)(As + row * 32 + i4 * 4) = v;
            }
        }
        // --- B tile: U_f[t][kc*32 + i][j] ---
#pragma unroll
        for (int l = 0; l < 4; ++l) {
            int idx = l * 256 + tid;
            int i = idx >> 5, j4 = idx & 31;
            float4 v = *(const float4*)(U_f + (size_t)t * HH * HH +
                                        (size_t)(kc * 32 + i) * 128 + j4 * 4);
            *(float4*)(Bs + i * 128 + j4 * 4) = v;
        }
        __syncthreads();
        // --- compute ---
#pragma unroll
        for (int i4 = 0; i4 < 8; ++i4) {
            ulonglong2 b0 = *(const ulonglong2*)(Bs + (i4 * 4 + 0) * 128 + lane * 4);
            ulonglong2 b1 = *(const ulonglong2*)(Bs + (i4 * 4 + 1) * 128 + lane * 4);
            ulonglong2 b2 = *(const ulonglong2*)(Bs + (i4 * 4 + 2) * 128 + lane * 4);
            ulonglong2 b3 = *(const ulonglong2*)(Bs + (i4 * 4 + 3) * 128 + lane * 4);
#pragma unroll
            for (int r = 0; r < 16; ++r) {
                float4 a = *(const float4*)(As + (w * 16 + r) * 32 + i4 * 4);
                ull ax = bcast2(a.x), ay = bcast2(a.y), az = bcast2(a.z), aw = bcast2(a.w);
                ffma2(acc[r][0], ax, b0.x); ffma2(acc[r][1], ax, b0.y);
                ffma2(acc[r][0], ay, b1.x); ffma2(acc[r][1], ay, b1.y);
                ffma2(acc[r][0], az, b2.x); ffma2(acc[r][1], az, b2.y);
                ffma2(acc[r][0], aw, b3.x); ffma2(acc[r][1], aw, b3.y);
            }
        }
    }
    // --- epilogue: f = sigmoid(logit + f_input + b_f); c_aggr = sum_k f*c ---
    float4 bf = *(const float4*)(b_f + t * 128 + lane * 4);
#pragma unroll
    for (int half = 0; half < 2; ++half) {
        int ln = 2 * w + half;
        if (m0 + ln >= cnt) continue;
        int n = perm[ln];
        float4 fin = *(const float4*)(f_input + (size_t)n * 128 + lane * 4);
        float cf0 = 0.f, cf1 = 0.f, cf2 = 0.f, cf3 = 0.f;
#pragma unroll
        for (int k = 0; k < 8; ++k) {
            int r = half * 8 + k;
            float2 p0 = unpack2(acc[r][0]), p1 = unpack2(acc[r][1]);
            float4 cv = *(const float4*)(c + (size_t)n * 1024 + k * 128 + lane * 4);
            cf0 += __fdividef(cv.x, 1.f + __expf(-(p0.x + fin.x + bf.x)));
            cf1 += __fdividef(cv.y, 1.f + __expf(-(p0.y + fin.y + bf.y)));
            cf2 += __fdividef(cv.z, 1.f + __expf(-(p1.x + fin.z + bf.z)));
            cf3 += __fdividef(cv.w, 1.f + __expf(-(p1.y + fin.w + bf.w)));
        }
        *(float4*)(out + (size_t)n * 512 + 384 + lane * 4) = make_float4(cf0, cf1, cf2, cf3);
    }
}

// ---------------------------------------------------------------------------
extern "C" void kernel_launch(void* const* d_in, const int* in_sizes, int n_in,
                              void* d_out, int out_size) {
    const float* h       = (const float*)d_in[0];   // [N, K, H]
    const float* c       = (const float*)d_in[1];   // [N, K, H]
    const float* f_input = (const float*)d_in[2];   // [N, H]
    const int*   type_id = (const int*)d_in[3];     // [N]
    const float* U_iou   = (const float*)d_in[4];   // [T, H, 3H]
    const float* b_iou   = (const float*)d_in[5];   // [T, 3H]
    const float* U_f     = (const float*)d_in[6];   // [T, H, H]
    const float* b_f     = (const float*)d_in[7];   // [T, H]
    float* out = (float*)d_out;                     // [N, 4H]

    k_zero<<<1, 32>>>();
    k_scatter<<<NN / 256, 256>>>(type_id);
    k_hsum<<<(NN * HH / 4) / 256, 256>>>(h);
    k_iou<<<dim3(NN / 128, 3, TT), 256>>>(U_iou, b_iou, out);
    k_fgate<<<dim3(NN / 16, 1, TT), 256>>>(h, c, f_input, U_f, b_f, out);
}